// round 4
// baseline (speedup 1.0000x reference)
#include <cuda_runtime.h>

#define NRAYS 16384
#define NSTEPS 100
#define STH 5e-5f

// ---------------- device scratch (no allocations allowed) ----------------
__device__ float g_c1[64];
__device__ float g_acc_s[NRAYS];
__device__ float g_acc_e[NRAYS];
__device__ unsigned int g_flags[NRAYS];          // bit0 = sampler_mask, bit1 = network_object_mask
__device__ float g_sdfval[NSTEPS * NRAYS];       // sample-major: [s*NRAYS + r]
__device__ int g_mask_mode;                      // 0=bytes, 1=int32 words, 2=float32 words

// Exact XLA-style elementwise ops: separate RN mul/add (no FMA contraction).
#define MUL(a, b) __fmul_rn((a), (b))
#define ADD(a, b) __fadd_rn((a), (b))
#define SUB(a, b) __fsub_rn((a), (b))

// ---------------- shared weight cache ----------------
struct SdfShared {
    float W1[192];      // first 3 rows of W1 (3 x 64), row-major
    float c1[64];       // b1 + id@W1[3:35] + exp@W1[35:67]
    float b2[64];
    float W3[64];
    float W2[64 * 64];  // row-major [k][j]
    float cam[3];
    float b3;
};

__device__ __forceinline__ float softplusf(float x) {
    // jax.nn.softplus = logaddexp(x,0) = max(x,0) + log1p(exp(-|x|)).
    // expf/log1pf lower to the same libdevice code XLA emits.
    return ADD(fmaxf(x, 0.0f), log1pf(expf(-fabsf(x))));
}

__device__ __forceinline__ void load_shared(SdfShared* sh, const float* W1, const float* W2,
                                            const float* b2, const float* W3, const float* b3,
                                            const float* cam) {
    int t = threadIdx.x, nt = blockDim.x;
    for (int i = t; i < 64 * 64; i += nt) sh->W2[i] = W2[i];
    for (int i = t; i < 192; i += nt) sh->W1[i] = W1[i];
    for (int i = t; i < 64; i += nt) {
        sh->c1[i] = g_c1[i];
        sh->b2[i] = b2[i];
        sh->W3[i] = W3[i];
    }
    if (t == 0) {
        sh->b3 = b3[0];
        sh->cam[0] = cam[0]; sh->cam[1] = cam[1]; sh->cam[2] = cam[2];
    }
    __syncthreads();
}

// One MLP-perturbed sphere SDF evaluation. The MLP (delta) path is attenuated
// 20x by 0.05*tanh -> FMA accumulation is fine there. The geometric |p| path
// uses exact separate-rounded ops to match XLA bit-for-bit.
__device__ __noinline__ float sdf_eval(const SdfShared* __restrict__ sh,
                                       float x, float y, float z) {
    float acc[64];
#pragma unroll
    for (int j = 0; j < 64; ++j) acc[j] = 0.0f;
#pragma unroll 4
    for (int k = 0; k < 64; ++k) {
        float pre = sh->c1[k];
        pre = fmaf(x, sh->W1[k], pre);
        pre = fmaf(y, sh->W1[64 + k], pre);
        pre = fmaf(z, sh->W1[128 + k], pre);
        float hk = softplusf(pre);
        const float4* w = (const float4*)(sh->W2 + k * 64);
#pragma unroll
        for (int j4 = 0; j4 < 16; ++j4) {
            float4 wv = w[j4];
            acc[4 * j4 + 0] = fmaf(hk, wv.x, acc[4 * j4 + 0]);
            acc[4 * j4 + 1] = fmaf(hk, wv.y, acc[4 * j4 + 1]);
            acc[4 * j4 + 2] = fmaf(hk, wv.z, acc[4 * j4 + 2]);
            acc[4 * j4 + 3] = fmaf(hk, wv.w, acc[4 * j4 + 3]);
        }
    }
    float d0 = 0.f, d1 = 0.f, d2 = 0.f, d3 = 0.f;
#pragma unroll
    for (int j = 0; j < 64; j += 4) {   // bias added after GEMM (matches XLA h@W2 + b2)
        d0 = fmaf(softplusf(ADD(acc[j + 0], sh->b2[j + 0])), sh->W3[j + 0], d0);
        d1 = fmaf(softplusf(ADD(acc[j + 1], sh->b2[j + 1])), sh->W3[j + 1], d1);
        d2 = fmaf(softplusf(ADD(acc[j + 2], sh->b2[j + 2])), sh->W3[j + 2], d2);
        d3 = fmaf(softplusf(ADD(acc[j + 3], sh->b2[j + 3])), sh->W3[j + 3], d3);
    }
    float delta = ADD(((d0 + d1) + (d2 + d3)), sh->b3);
    // geometric path: sum(pts*pts) + 1e-12, sqrt, -0.5, +0.05*tanh — exact order
    float r2 = ADD(ADD(ADD(MUL(x, x), MUL(y, y)), MUL(z, z)), 1e-12f);
    return ADD(SUB(sqrtf(r2), 0.5f), MUL(0.05f, tanhf(delta)));
}

// ---------------- phase 0a: fold latents into c1 ----------------
__global__ void prep_kernel(const float* __restrict__ W1, const float* __restrict__ b1,
                            const float* __restrict__ idl, const float* __restrict__ expl) {
    int j = threadIdx.x;   // 64 threads
    float c = b1[j];
#pragma unroll 8
    for (int k = 0; k < 32; ++k) c = fmaf(idl[k], W1[(3 + k) * 64 + j], c);
#pragma unroll 8
    for (int k = 0; k < 32; ++k) c = fmaf(expl[k], W1[(35 + k) * 64 + j], c);
    g_c1[j] = c;
}

// ---------------- phase 0b: detect object_mask element layout ----------------
__global__ void detect_mask_kernel(const unsigned int* __restrict__ m) {
    __shared__ int any_big, any_f1, any_other;
    if (threadIdx.x == 0) { any_big = 0; any_f1 = 0; any_other = 0; }
    __syncthreads();
    for (int i = threadIdx.x; i < NRAYS / 4; i += blockDim.x) {
        unsigned v = m[i];
        if (v > 1u) {
            any_big = 1;
            if (v == 0x3F800000u) any_f1 = 1;
            else any_other = 1;
        }
    }
    __syncthreads();
    if (threadIdx.x == 0) {
        int mode;
        if (!any_big) mode = 1;                      // all {0,1}: int32 words
        else if (any_f1 && !any_other) mode = 2;     // {0.0f,1.0f} words
        else mode = 0;                               // packed bytes
        g_mask_mode = mode;
    }
}

// ---------------- phase 1: sphere tracing, 2 threads/ray (start & end chains) ----------------
__global__ void trace_kernel(const float* __restrict__ cam_loc, const float* __restrict__ dirs,
                             const float* __restrict__ W1, const float* __restrict__ W2,
                             const float* __restrict__ b2, const float* __restrict__ W3,
                             const float* __restrict__ b3) {
    __shared__ SdfShared sh;
    load_shared(&sh, W1, W2, b2, W3, b3, cam_loc);

    int tid = blockIdx.x * blockDim.x + threadIdx.x;
    int r = tid >> 1;
    int c = tid & 1;                 // 0 = start chain, 1 = end chain
    float dx = dirs[3 * r + 0], dy = dirs[3 * r + 1], dz = dirs[3 * r + 2];
    float cx = sh.cam[0], cy = sh.cam[1], cz = sh.cam[2];

    // einsum products then left-to-right reduce, no fma (matches XLA)
    float rcd = ADD(ADD(MUL(dx, cx), MUL(dy, cy)), MUL(dz, cz));
    float cam2 = ADD(ADD(MUL(cx, cx), MUL(cy, cy)), MUL(cz, cz));
    float under = SUB(MUL(rcd, rcd), SUB(cam2, 1.0f));   // R = 1
    bool mask = under > 0.0f;
    float sq = sqrtf(mask ? under : 1.0f);
    float acc = mask ? fmaxf(SUB((c ? sq : -sq), rcd), 0.0f) : 0.0f;
    bool unfin = mask;

    float next = 0.0f;
    if (unfin)
        next = sdf_eval(&sh, ADD(cx, MUL(acc, dx)), ADD(cy, MUL(acc, dy)), ADD(cz, MUL(acc, dz)));
    float next_o = __shfl_xor_sync(0xffffffffu, next, 1);
    bool no_int = (next < 0.0f) && (next_o < 0.0f);

    for (int it = 0;; ++it) {
        bool adv = unfin && (next > STH);       // cs > threshold
        unfin = adv;
        if (it == 10) break;                    // SPHERE_TRACING_ITERS
        float cs = adv ? fminf(next, 0.5f) : 0.0f;
        float st = MUL(1.2f, cs);
        acc = c ? SUB(acc, st) : ADD(acc, st);  // acc_s + 1.2cs / acc_e - 1.2ce
        next = unfin ? sdf_eval(&sh, ADD(cx, MUL(acc, dx)), ADD(cy, MUL(acc, dy)),
                                ADD(cz, MUL(acc, dz)))
                     : 0.0f;
        if (next < 0.0f) {                      // line-search (1 iter, step=0.5)
            float ls = MUL(0.5f, cs);
            acc = c ? ADD(acc, ls) : SUB(acc, ls);
            next = sdf_eval(&sh, ADD(cx, MUL(acc, dx)), ADD(cy, MUL(acc, dy)),
                            ADD(cz, MUL(acc, dz)));
        }
        float acc_o = __shfl_xor_sync(0xffffffffu, acc, 1);
        bool inside = c ? (acc_o < acc) : (acc < acc_o);
        unfin = unfin && inside;
    }

    float acc_o = __shfl_xor_sync(0xffffffffu, acc, 1);
    if (c == 0) {
        g_acc_s[r] = acc;
        g_acc_e[r] = acc_o;
        bool netobj = (acc < acc_o) && !no_int;
        g_flags[r] = (unfin ? 1u : 0u) | (netobj ? 2u : 0u);
    }
}

// ---------------- phase 2: 100 uniform samples per sampler ray ----------------
__global__ void sample_kernel(const float* __restrict__ cam_loc, const float* __restrict__ dirs,
                              const float* __restrict__ W1, const float* __restrict__ W2,
                              const float* __restrict__ b2, const float* __restrict__ W3,
                              const float* __restrict__ b3) {
    __shared__ SdfShared sh;
    load_shared(&sh, W1, W2, b2, W3, b3, cam_loc);

    int idx = blockIdx.x * blockDim.x + threadIdx.x;     // idx = s*NRAYS + r
    int r = idx & (NRAYS - 1);
    int s = idx >> 14;
    if (!(g_flags[r] & 1u)) {                 // non-sampler rays: values are dead downstream
        g_sdfval[idx] = 0.0f;
        return;
    }
    float mn = g_acc_s[r], mx = g_acc_e[r];
    float t = MUL((float)s, 1.0f / 99.0f);               // linspace: iota * step
    float d = ADD(mn, MUL(t, SUB(mx, mn)));
    float dx = dirs[3 * r + 0], dy = dirs[3 * r + 1], dz = dirs[3 * r + 2];
    float x = ADD(sh.cam[0], MUL(d, dx));
    float y = ADD(sh.cam[1], MUL(d, dy));
    float z = ADD(sh.cam[2], MUL(d, dz));
    g_sdfval[idx] = sdf_eval(&sh, x, y, z);
}

// ---------------- phase 3: argmins + secant + outputs ----------------
__global__ void finish_kernel(const float* __restrict__ cam_loc, const float* __restrict__ dirs,
                              const void* __restrict__ objmask,
                              const float* __restrict__ W1, const float* __restrict__ W2,
                              const float* __restrict__ b2, const float* __restrict__ W3,
                              const float* __restrict__ b3, float* __restrict__ out) {
    __shared__ SdfShared sh;
    load_shared(&sh, W1, W2, b2, W3, b3, cam_loc);

    int r = blockIdx.x * blockDim.x + threadIdx.x;
    unsigned f = g_flags[r];
    float dx = dirs[3 * r + 0], dy = dirs[3 * r + 1], dz = dirs[3 * r + 2];
    float cx = sh.cam[0], cy = sh.cam[1], cz = sh.cam[2];
    float acc_s = g_acc_s[r];

    float out_d, out_m;
    if (!(f & 1u)) {
        out_d = acc_s;                                   // dis = acc_start
        out_m = (f & 2u) ? 1.0f : 0.0f;                  // network_object_mask
    } else {
        float mn = acc_s, mx = g_acc_e[r];
        float dlt = SUB(mx, mn);
        float best1 = 1e30f; int ind = 0;                // argmin of sign(sdf)*w (first)
        float best2 = 1e30f; int ind_out = 0;            // argmin of sdf (first)
        for (int s = 0; s < NSTEPS; ++s) {
            float v = g_sdfval[s * NRAYS + r];           // coalesced: lanes = consecutive r
            float sg = (v > 0.f) ? 1.f : ((v < 0.f) ? -1.f : 0.f);
            float m1 = sg * (float)(NSTEPS - s);
            if (m1 < best1) { best1 = m1; ind = s; }
            if (v < best2) { best2 = v; ind_out = s; }
        }
        float d_at = ADD(mn, MUL(MUL((float)ind, 1.f / 99.f), dlt));
        float sdf_at = g_sdfval[ind * NRAYS + r];
        bool net_surf = sdf_at < 0.f;
        int mode = g_mask_mode;
        bool obj = (mode == 1) ? (((const int*)objmask)[r] != 0)
                 : (mode == 2) ? (((const float*)objmask)[r] != 0.0f)
                               : (((const unsigned char*)objmask)[r] != 0);
        bool p_out = !(obj && net_surf);
        float samp_d = p_out ? ADD(mn, MUL(MUL((float)ind_out, 1.f / 99.f), dlt)) : d_at;

        if (net_surf && obj) {                           // secant refinement
            int ind_lo = (ind == 0) ? (NSTEPS - 1) : (ind - 1);
            float z_high = d_at, sdf_high = sdf_at;
            float z_low = ADD(mn, MUL(MUL((float)ind_lo, 1.f / 99.f), dlt));
            float sdf_low = g_sdfval[ind_lo * NRAYS + r];
            float denom = SUB(sdf_high, sdf_low);
            float z_pred = ADD(__fdiv_rn(MUL(-sdf_low, SUB(z_high, z_low)),
                                         (denom == 0.f) ? 1.f : denom), z_low);
            for (int i = 0; i < 8; ++i) {
                float sm = sdf_eval(&sh, ADD(cx, MUL(z_pred, dx)), ADD(cy, MUL(z_pred, dy)),
                                    ADD(cz, MUL(z_pred, dz)));
                if (sm > 0.f) { z_low = z_pred; sdf_low = sm; }
                if (sm < 0.f) { z_high = z_pred; sdf_high = sm; }
                denom = SUB(sdf_high, sdf_low);
                z_pred = ADD(__fdiv_rn(MUL(-sdf_low, SUB(z_high, z_low)),
                                       (denom == 0.f) ? 1.f : denom), z_low);
            }
            samp_d = z_pred;
        }
        out_d = samp_d;
        out_m = net_surf ? 1.0f : 0.0f;                  // sampler_net_obj_mask
    }

    // outputs: pts [N,3], mask [N], dis [N], concatenated
    out[3 * r + 0] = ADD(cx, MUL(out_d, dx));
    out[3 * r + 1] = ADD(cy, MUL(out_d, dy));
    out[3 * r + 2] = ADD(cz, MUL(out_d, dz));
    out[3 * NRAYS + r] = out_m;
    out[4 * NRAYS + r] = out_d;
}

extern "C" void kernel_launch(void* const* d_in, const int* in_sizes, int n_in,
                              void* d_out, int out_size) {
    const float* cam   = (const float*)d_in[0];
    const void*  omask = d_in[1];
    const float* dirs  = (const float*)d_in[2];
    const float* idl   = (const float*)d_in[3];
    const float* expl  = (const float*)d_in[4];
    const float* W1    = (const float*)d_in[5];
    const float* b1    = (const float*)d_in[6];
    const float* W2    = (const float*)d_in[7];
    const float* b2    = (const float*)d_in[8];
    const float* W3    = (const float*)d_in[9];
    const float* b3    = (const float*)d_in[10];
    float* out = (float*)d_out;

    prep_kernel<<<1, 64>>>(W1, b1, idl, expl);
    detect_mask_kernel<<<1, 256>>>((const unsigned int*)omask);
    trace_kernel<<<(2 * NRAYS) / 256, 256>>>(cam, dirs, W1, W2, b2, W3, b3);
    sample_kernel<<<(NSTEPS * NRAYS) / 256, 256>>>(cam, dirs, W1, W2, b2, W3, b3);
    finish_kernel<<<NRAYS / 128, 128>>>(cam, dirs, omask, W1, W2, b2, W3, b3, out);
}

// round 5
// speedup vs baseline: 1.4583x; 1.4583x over previous
#include <cuda_runtime.h>

#define NRAYS 16384
#define NSTEPS 100
#define STH 5e-5f

// ---------------- device scratch (no allocations allowed) ----------------
__device__ float g_c1[64];
__device__ float g_acc_s[NRAYS];
__device__ float g_acc_e[NRAYS];
__device__ unsigned int g_flags[NRAYS];          // bit0 = sampler_mask, bit1 = network_object_mask
__device__ float g_sdfval[NSTEPS * NRAYS];       // sample-major: [s*NRAYS + r]
__device__ int g_mask_mode;                      // 0=bytes, 1=int32 words, 2=float32 words

// Exact XLA-style elementwise ops: separate RN mul/add (no FMA contraction).
#define MUL(a, b) __fmul_rn((a), (b))
#define ADD(a, b) __fadd_rn((a), (b))
#define SUB(a, b) __fsub_rn((a), (b))

// Packed f32x2 ops (sm_100+). Each half rounds exactly like scalar IEEE FMA,
// so results are bit-identical to the scalar version — pure instruction-count win.
#define FMA2(acc, a, b) \
    asm("fma.rn.f32x2 %0, %1, %2, %0;" : "+l"(acc) : "l"(a), "l"(b))
#define PACK2(d, s) \
    asm("mov.b64 %0, {%1, %1};" : "=l"(d) : "r"(s))
#define UNPACK2(lo, hi, v) \
    asm("mov.b64 {%0, %1}, %2;" : "=r"(lo), "=r"(hi) : "l"(v))

// ---------------- shared weight cache ----------------
struct __align__(16) SdfShared {
    float W1[192];      // first 3 rows of W1 (3 x 64), row-major
    float c1[64];       // b1 + id@W1[3:35] + exp@W1[35:67]
    float b2[64];
    float W3[64];
    float W2[64 * 64];  // row-major [k][j]  (16B-aligned: offset 1536)
    float cam[3];
    float b3;
};

__device__ __forceinline__ float softplusf(float x) {
    // jax.nn.softplus = max(x,0) + log1p(exp(-|x|)); fast-math variant.
    // abs err ~2.5e-7 in h -> ~2.5e-8 in sdf after 0.05*tanh attenuation.
    return ADD(fmaxf(x, 0.0f), __logf(__fadd_rn(1.0f, __expf(-fabsf(x)))));
}

__device__ __forceinline__ void load_shared(SdfShared* sh, const float* W1, const float* W2,
                                            const float* b2, const float* W3, const float* b3,
                                            const float* cam) {
    int t = threadIdx.x, nt = blockDim.x;
    for (int i = t; i < 64 * 64; i += nt) sh->W2[i] = W2[i];
    for (int i = t; i < 192; i += nt) sh->W1[i] = W1[i];
    for (int i = t; i < 64; i += nt) {
        sh->c1[i] = g_c1[i];
        sh->b2[i] = b2[i];
        sh->W3[i] = W3[i];
    }
    if (t == 0) {
        sh->b3 = b3[0];
        sh->cam[0] = cam[0]; sh->cam[1] = cam[1]; sh->cam[2] = cam[2];
    }
    __syncthreads();
}

// One MLP-perturbed sphere SDF evaluation. Layer-2 GEMV in packed f32x2 FMA
// (bit-identical to scalar). Geometric |p| path in exact separate-rounded ops.
__device__ __noinline__ float sdf_eval(const SdfShared* __restrict__ sh,
                                       float x, float y, float z) {
    unsigned long long acc2[32];
#pragma unroll
    for (int m = 0; m < 32; ++m) acc2[m] = 0ull;
#pragma unroll 4
    for (int k = 0; k < 64; ++k) {
        float pre = sh->c1[k];
        pre = fmaf(x, sh->W1[k], pre);
        pre = fmaf(y, sh->W1[64 + k], pre);
        pre = fmaf(z, sh->W1[128 + k], pre);
        float hk = softplusf(pre);
        unsigned long long hk2;
        PACK2(hk2, __float_as_uint(hk));
        const ulonglong2* wrow = (const ulonglong2*)(sh->W2) + k * 16;
#pragma unroll
        for (int j = 0; j < 16; ++j) {
            ulonglong2 wv = wrow[j];
            FMA2(acc2[2 * j + 0], hk2, wv.x);
            FMA2(acc2[2 * j + 1], hk2, wv.y);
        }
    }
    // layer 3: same accumulation order as the scalar version (d0..d3 by j%4)
    float d0 = 0.f, d1 = 0.f, d2 = 0.f, d3 = 0.f;
#pragma unroll
    for (int m = 0; m < 32; m += 2) {
        unsigned l0, h0, l1, h1;
        UNPACK2(l0, h0, acc2[m]);
        UNPACK2(l1, h1, acc2[m + 1]);
        int j = 2 * m;   // j, j+1, j+2, j+3
        d0 = fmaf(softplusf(ADD(__uint_as_float(l0), sh->b2[j + 0])), sh->W3[j + 0], d0);
        d1 = fmaf(softplusf(ADD(__uint_as_float(h0), sh->b2[j + 1])), sh->W3[j + 1], d1);
        d2 = fmaf(softplusf(ADD(__uint_as_float(l1), sh->b2[j + 2])), sh->W3[j + 2], d2);
        d3 = fmaf(softplusf(ADD(__uint_as_float(h1), sh->b2[j + 3])), sh->W3[j + 3], d3);
    }
    float delta = ADD(((d0 + d1) + (d2 + d3)), sh->b3);
    // geometric path: sum(pts*pts) + 1e-12, sqrt, -0.5, +0.05*tanh — exact order
    float r2 = ADD(ADD(ADD(MUL(x, x), MUL(y, y)), MUL(z, z)), 1e-12f);
    return ADD(SUB(sqrtf(r2), 0.5f), MUL(0.05f, tanhf(delta)));
}

// ---------------- phase 0a: fold latents into c1 ----------------
__global__ void prep_kernel(const float* __restrict__ W1, const float* __restrict__ b1,
                            const float* __restrict__ idl, const float* __restrict__ expl) {
    int j = threadIdx.x;   // 64 threads
    float c = b1[j];
#pragma unroll 8
    for (int k = 0; k < 32; ++k) c = fmaf(idl[k], W1[(3 + k) * 64 + j], c);
#pragma unroll 8
    for (int k = 0; k < 32; ++k) c = fmaf(expl[k], W1[(35 + k) * 64 + j], c);
    g_c1[j] = c;
}

// ---------------- phase 0b: detect object_mask element layout ----------------
__global__ void detect_mask_kernel(const unsigned int* __restrict__ m) {
    __shared__ int any_big, any_f1, any_other;
    if (threadIdx.x == 0) { any_big = 0; any_f1 = 0; any_other = 0; }
    __syncthreads();
    for (int i = threadIdx.x; i < NRAYS / 4; i += blockDim.x) {
        unsigned v = m[i];
        if (v > 1u) {
            any_big = 1;
            if (v == 0x3F800000u) any_f1 = 1;
            else any_other = 1;
        }
    }
    __syncthreads();
    if (threadIdx.x == 0) {
        int mode;
        if (!any_big) mode = 1;                      // all {0,1}: int32 words
        else if (any_f1 && !any_other) mode = 2;     // {0.0f,1.0f} words
        else mode = 0;                               // packed bytes
        g_mask_mode = mode;
    }
}

// ---------------- phase 1: sphere tracing, 2 threads/ray (start & end chains) ----------------
__global__ void trace_kernel(const float* __restrict__ cam_loc, const float* __restrict__ dirs,
                             const float* __restrict__ W1, const float* __restrict__ W2,
                             const float* __restrict__ b2, const float* __restrict__ W3,
                             const float* __restrict__ b3) {
    __shared__ SdfShared sh;
    load_shared(&sh, W1, W2, b2, W3, b3, cam_loc);

    int tid = blockIdx.x * blockDim.x + threadIdx.x;
    int r = tid >> 1;
    int c = tid & 1;                 // 0 = start chain, 1 = end chain
    float dx = dirs[3 * r + 0], dy = dirs[3 * r + 1], dz = dirs[3 * r + 2];
    float cx = sh.cam[0], cy = sh.cam[1], cz = sh.cam[2];

    // einsum products then left-to-right reduce, no fma (matches XLA)
    float rcd = ADD(ADD(MUL(dx, cx), MUL(dy, cy)), MUL(dz, cz));
    float cam2 = ADD(ADD(MUL(cx, cx), MUL(cy, cy)), MUL(cz, cz));
    float under = SUB(MUL(rcd, rcd), SUB(cam2, 1.0f));   // R = 1
    bool mask = under > 0.0f;
    float sq = sqrtf(mask ? under : 1.0f);
    float acc = mask ? fmaxf(SUB((c ? sq : -sq), rcd), 0.0f) : 0.0f;
    bool unfin = mask;

    float next = 0.0f;
    if (unfin)
        next = sdf_eval(&sh, ADD(cx, MUL(acc, dx)), ADD(cy, MUL(acc, dy)), ADD(cz, MUL(acc, dz)));
    float next_o = __shfl_xor_sync(0xffffffffu, next, 1);
    bool no_int = (next < 0.0f) && (next_o < 0.0f);

    for (int it = 0;; ++it) {
        bool adv = unfin && (next > STH);       // cs > threshold
        unfin = adv;
        if (it == 10) break;                    // SPHERE_TRACING_ITERS
        float cs = adv ? fminf(next, 0.5f) : 0.0f;
        float st = MUL(1.2f, cs);
        acc = c ? SUB(acc, st) : ADD(acc, st);  // acc_s + 1.2cs / acc_e - 1.2ce
        next = unfin ? sdf_eval(&sh, ADD(cx, MUL(acc, dx)), ADD(cy, MUL(acc, dy)),
                                ADD(cz, MUL(acc, dz)))
                     : 0.0f;
        if (next < 0.0f) {                      // line-search (1 iter, step=0.5)
            float ls = MUL(0.5f, cs);
            acc = c ? ADD(acc, ls) : SUB(acc, ls);
            next = sdf_eval(&sh, ADD(cx, MUL(acc, dx)), ADD(cy, MUL(acc, dy)),
                            ADD(cz, MUL(acc, dz)));
        }
        float acc_o = __shfl_xor_sync(0xffffffffu, acc, 1);
        bool inside = c ? (acc_o < acc) : (acc < acc_o);
        unfin = unfin && inside;
    }

    float acc_o = __shfl_xor_sync(0xffffffffu, acc, 1);
    if (c == 0) {
        g_acc_s[r] = acc;
        g_acc_e[r] = acc_o;
        bool netobj = (acc < acc_o) && !no_int;
        g_flags[r] = (unfin ? 1u : 0u) | (netobj ? 2u : 0u);
    }
}

// ---------------- phase 2: 100 uniform samples per sampler ray ----------------
__global__ void sample_kernel(const float* __restrict__ cam_loc, const float* __restrict__ dirs,
                              const float* __restrict__ W1, const float* __restrict__ W2,
                              const float* __restrict__ b2, const float* __restrict__ W3,
                              const float* __restrict__ b3) {
    __shared__ SdfShared sh;
    load_shared(&sh, W1, W2, b2, W3, b3, cam_loc);

    int idx = blockIdx.x * blockDim.x + threadIdx.x;     // idx = s*NRAYS + r
    int r = idx & (NRAYS - 1);
    int s = idx >> 14;
    if (!(g_flags[r] & 1u)) return;           // non-sampler rays: values never read downstream
    float mn = g_acc_s[r], mx = g_acc_e[r];
    float t = MUL((float)s, 1.0f / 99.0f);               // linspace: iota * step
    float d = ADD(mn, MUL(t, SUB(mx, mn)));
    float dx = dirs[3 * r + 0], dy = dirs[3 * r + 1], dz = dirs[3 * r + 2];
    float x = ADD(sh.cam[0], MUL(d, dx));
    float y = ADD(sh.cam[1], MUL(d, dy));
    float z = ADD(sh.cam[2], MUL(d, dz));
    g_sdfval[idx] = sdf_eval(&sh, x, y, z);
}

// ---------------- phase 3: argmins + secant + outputs ----------------
__global__ void finish_kernel(const float* __restrict__ cam_loc, const float* __restrict__ dirs,
                              const void* __restrict__ objmask,
                              const float* __restrict__ W1, const float* __restrict__ W2,
                              const float* __restrict__ b2, const float* __restrict__ W3,
                              const float* __restrict__ b3, float* __restrict__ out) {
    __shared__ SdfShared sh;
    load_shared(&sh, W1, W2, b2, W3, b3, cam_loc);

    int r = blockIdx.x * blockDim.x + threadIdx.x;
    unsigned f = g_flags[r];
    float dx = dirs[3 * r + 0], dy = dirs[3 * r + 1], dz = dirs[3 * r + 2];
    float cx = sh.cam[0], cy = sh.cam[1], cz = sh.cam[2];
    float acc_s = g_acc_s[r];

    float out_d, out_m;
    if (!(f & 1u)) {
        out_d = acc_s;                                   // dis = acc_start
        out_m = (f & 2u) ? 1.0f : 0.0f;                  // network_object_mask
    } else {
        float mn = acc_s, mx = g_acc_e[r];
        float dlt = SUB(mx, mn);
        float best1 = 1e30f; int ind = 0;                // argmin of sign(sdf)*w (first)
        float best2 = 1e30f; int ind_out = 0;            // argmin of sdf (first)
        for (int s = 0; s < NSTEPS; ++s) {
            float v = g_sdfval[s * NRAYS + r];           // coalesced: lanes = consecutive r
            float sg = (v > 0.f) ? 1.f : ((v < 0.f) ? -1.f : 0.f);
            float m1 = sg * (float)(NSTEPS - s);
            if (m1 < best1) { best1 = m1; ind = s; }
            if (v < best2) { best2 = v; ind_out = s; }
        }
        float d_at = ADD(mn, MUL(MUL((float)ind, 1.f / 99.f), dlt));
        float sdf_at = g_sdfval[ind * NRAYS + r];
        bool net_surf = sdf_at < 0.f;
        int mode = g_mask_mode;
        bool obj = (mode == 1) ? (((const int*)objmask)[r] != 0)
                 : (mode == 2) ? (((const float*)objmask)[r] != 0.0f)
                               : (((const unsigned char*)objmask)[r] != 0);
        bool p_out = !(obj && net_surf);
        float samp_d = p_out ? ADD(mn, MUL(MUL((float)ind_out, 1.f / 99.f), dlt)) : d_at;

        if (net_surf && obj) {                           // secant refinement
            int ind_lo = (ind == 0) ? (NSTEPS - 1) : (ind - 1);
            float z_high = d_at, sdf_high = sdf_at;
            float z_low = ADD(mn, MUL(MUL((float)ind_lo, 1.f / 99.f), dlt));
            float sdf_low = g_sdfval[ind_lo * NRAYS + r];
            float denom = SUB(sdf_high, sdf_low);
            float z_pred = ADD(__fdiv_rn(MUL(-sdf_low, SUB(z_high, z_low)),
                                         (denom == 0.f) ? 1.f : denom), z_low);
            for (int i = 0; i < 8; ++i) {
                float sm = sdf_eval(&sh, ADD(cx, MUL(z_pred, dx)), ADD(cy, MUL(z_pred, dy)),
                                    ADD(cz, MUL(z_pred, dz)));
                if (sm > 0.f) { z_low = z_pred; sdf_low = sm; }
                if (sm < 0.f) { z_high = z_pred; sdf_high = sm; }
                denom = SUB(sdf_high, sdf_low);
                z_pred = ADD(__fdiv_rn(MUL(-sdf_low, SUB(z_high, z_low)),
                                       (denom == 0.f) ? 1.f : denom), z_low);
            }
            samp_d = z_pred;
        }
        out_d = samp_d;
        out_m = net_surf ? 1.0f : 0.0f;                  // sampler_net_obj_mask
    }

    // outputs: pts [N,3], mask [N], dis [N], concatenated
    out[3 * r + 0] = ADD(cx, MUL(out_d, dx));
    out[3 * r + 1] = ADD(cy, MUL(out_d, dy));
    out[3 * r + 2] = ADD(cz, MUL(out_d, dz));
    out[3 * NRAYS + r] = out_m;
    out[4 * NRAYS + r] = out_d;
}

extern "C" void kernel_launch(void* const* d_in, const int* in_sizes, int n_in,
                              void* d_out, int out_size) {
    const float* cam   = (const float*)d_in[0];
    const void*  omask = d_in[1];
    const float* dirs  = (const float*)d_in[2];
    const float* idl   = (const float*)d_in[3];
    const float* expl  = (const float*)d_in[4];
    const float* W1    = (const float*)d_in[5];
    const float* b1    = (const float*)d_in[6];
    const float* W2    = (const float*)d_in[7];
    const float* b2    = (const float*)d_in[8];
    const float* W3    = (const float*)d_in[9];
    const float* b3    = (const float*)d_in[10];
    float* out = (float*)d_out;

    prep_kernel<<<1, 64>>>(W1, b1, idl, expl);
    detect_mask_kernel<<<1, 256>>>((const unsigned int*)omask);
    trace_kernel<<<(2 * NRAYS) / 256, 256>>>(cam, dirs, W1, W2, b2, W3, b3);
    sample_kernel<<<(NSTEPS * NRAYS) / 256, 256>>>(cam, dirs, W1, W2, b2, W3, b3);
    finish_kernel<<<NRAYS / 128, 128>>>(cam, dirs, omask, W1, W2, b2, W3, b3, out);
}